// round 7
// baseline (speedup 1.0000x reference)
#include <cuda_runtime.h>
#include <cuda_bf16.h>
#include <cstdint>

// ---------------------------------------------------------------------------
// GINConvolution:
//   h   = x @ W                      [N,128]
//   agg[i] = sum_{e: row[e]==i} vals[e] * h[col[e]]
//   out = relu((1+eps)*h + agg + bias)
//
// Memory plan (statics kept at 39.6 MB, proven safe in R6):
//   d_out holds h after the GEMM; the final result overwrites it in two
//   64-column phases. g_s (25.6MB) holds the h-half being finalized.
//   CSR: g_cnt/g_off/g_cur (1.2MB) + g_edges packed (col,val) (12.8MB).
// Launch order (single stream, serialized):
//   zero -> hist -> scan -> scatter -> gemm -> aggA -> copy -> aggB
// ---------------------------------------------------------------------------

#define N_NODES_MAX 100000
#define N_EDGES_MAX 1600000
#define UNITS 128
#define HALF 64

__device__ float g_s[N_NODES_MAX * HALF];   // 25.6MB scratch: current h-half
__device__ int   g_cnt[N_NODES_MAX];
__device__ int   g_off[N_NODES_MAX + 1];
__device__ int   g_cur[N_NODES_MAX];
__device__ int2  g_edges[N_EDGES_MAX];      // (col, val-bits)

// ---------------------------------------------------------------------------
// K1: tiled fp32 GEMM (proven 78-reg variant). Writes full h to d_out and
// the first 64 columns to g_s (phase-A scratch).
// ---------------------------------------------------------------------------
#define TM 64

__global__ __launch_bounds__(256) void gin_gemm_kernel(
    const float* __restrict__ x,
    const float* __restrict__ W,
    float* __restrict__ h_out,
    int n_nodes)
{
    __shared__ float xs[TM][UNITS];

    const int block_row = blockIdx.x * TM;
    const int tid = threadIdx.x;

    {   // load x tile as float4 (zero-pad tail rows)
        const float4* x4 = reinterpret_cast<const float4*>(x);
        float4* xs4 = reinterpret_cast<float4*>(&xs[0][0]);
        for (int i = tid; i < TM * 32; i += 256) {
            int gr = block_row + (i >> 5);
            float4 v = make_float4(0.f, 0.f, 0.f, 0.f);
            if (gr < n_nodes) v = x4[gr * 32 + (i & 31)];
            xs4[i] = v;
        }
    }
    __syncthreads();

    const int tx = tid & 31;   // 4 cols: 4tx..4tx+3
    const int ty = tid >> 5;   // 8 rows: ty + 8i

    float acc[8][4];
    #pragma unroll
    for (int i = 0; i < 8; i++)
        #pragma unroll
        for (int j = 0; j < 4; j++) acc[i][j] = 0.f;

    const float4* W4 = reinterpret_cast<const float4*>(W);

    #pragma unroll 4
    for (int k = 0; k < UNITS; k++) {
        float4 w = W4[k * 32 + tx];
        #pragma unroll
        for (int i = 0; i < 8; i++) {
            float a = xs[ty + 8 * i][k];   // warp-broadcast
            acc[i][0] += a * w.x;
            acc[i][1] += a * w.y;
            acc[i][2] += a * w.z;
            acc[i][3] += a * w.w;
        }
    }

    float4* h4 = reinterpret_cast<float4*>(h_out);
    float4* s4 = reinterpret_cast<float4*>(g_s);
    #pragma unroll
    for (int i = 0; i < 8; i++) {
        int gr = block_row + ty + 8 * i;
        if (gr < n_nodes) {
            float4 hv = make_float4(acc[i][0], acc[i][1], acc[i][2], acc[i][3]);
            h4[gr * 32 + tx] = hv;
            if (tx < 16) s4[gr * 16 + tx] = hv;   // h[:,0:64] -> scratch
        }
    }
}

// ---------------------------------------------------------------------------
// K2: zero counters
// ---------------------------------------------------------------------------
__global__ __launch_bounds__(256) void gin_zero_kernel(int n_nodes)
{
    int i = blockIdx.x * blockDim.x + threadIdx.x;
    if (i < n_nodes) g_cnt[i] = 0;
}

// ---------------------------------------------------------------------------
// K3: histogram of row indices
// ---------------------------------------------------------------------------
__global__ __launch_bounds__(256) void gin_hist_kernel(
    const int* __restrict__ row, int n_edges)
{
    int e = blockIdx.x * blockDim.x + threadIdx.x;
    if (e < n_edges) atomicAdd(&g_cnt[row[e]], 1);
}

// ---------------------------------------------------------------------------
// K4: single-block exclusive scan (1024 threads, chunked)
// ---------------------------------------------------------------------------
__global__ __launch_bounds__(1024) void gin_scan_kernel(int n_nodes)
{
    __shared__ int ssum[1024];
    const int t = threadIdx.x;
    const int C = (n_nodes + 1023) / 1024;
    const int s = min(t * C, n_nodes);
    const int e = min(s + C, n_nodes);

    int local = 0;
    for (int i = s; i < e; i++) local += g_cnt[i];
    ssum[t] = local;
    __syncthreads();

    for (int off = 1; off < 1024; off <<= 1) {
        int v = (t >= off) ? ssum[t - off] : 0;
        __syncthreads();
        ssum[t] += v;
        __syncthreads();
    }

    int base = (t == 0) ? 0 : ssum[t - 1];
    for (int i = s; i < e; i++) {
        g_off[i] = base;
        g_cur[i] = base;
        base += g_cnt[i];
    }
    if (t == 0) g_off[n_nodes] = ssum[1023];
}

// ---------------------------------------------------------------------------
// K5: scatter edges into CSR order (packed 8B records)
// ---------------------------------------------------------------------------
__global__ __launch_bounds__(256) void gin_scatter_kernel(
    const float* __restrict__ vals,
    const int* __restrict__ row,
    const int* __restrict__ col,
    int n_edges)
{
    int e = blockIdx.x * blockDim.x + threadIdx.x;
    if (e >= n_edges) return;
    int r = row[e];
    int pos = atomicAdd(&g_cur[r], 1);
    g_edges[pos] = make_int2(col[e], __float_as_int(vals[e]));
}

// ---------------------------------------------------------------------------
// K6: per-phase aggregation, 4-edge-unrolled for MLP.
// Warp per node, lane handles float2 (64 cols of this phase).
//   out[i][p*64 .. p*64+63] = relu((1+eps)*h_half[i] + sum val*h_half[col] + b)
// ---------------------------------------------------------------------------
__global__ __launch_bounds__(256) void gin_agg_kernel(
    const float* __restrict__ bias,
    const float* __restrict__ eps,
    float* __restrict__ out,
    int n_nodes, int phase)
{
    const int node = (blockIdx.x * blockDim.x + threadIdx.x) >> 5;
    if (node >= n_nodes) return;
    const int lane = threadIdx.x & 31;

    const int beg = g_off[node];
    const int end = g_off[node + 1];

    const float2* s2 = reinterpret_cast<const float2*>(g_s);

    float a0x = 0.f, a0y = 0.f;
    float a1x = 0.f, a1y = 0.f;

    int e = beg;
    // 4-wide unroll: 4 independent gathers in flight per warp (MLP=4)
    for (; e + 4 <= end; e += 4) {
        int2 c0 = g_edges[e + 0];
        int2 c1 = g_edges[e + 1];
        int2 c2 = g_edges[e + 2];
        int2 c3 = g_edges[e + 3];
        float2 h0 = s2[(size_t)c0.x * 32 + lane];
        float2 h1 = s2[(size_t)c1.x * 32 + lane];
        float2 h2 = s2[(size_t)c2.x * 32 + lane];
        float2 h3 = s2[(size_t)c3.x * 32 + lane];
        float v0 = __int_as_float(c0.y);
        float v1 = __int_as_float(c1.y);
        float v2 = __int_as_float(c2.y);
        float v3 = __int_as_float(c3.y);
        a0x = fmaf(v0, h0.x, a0x);  a0y = fmaf(v0, h0.y, a0y);
        a1x = fmaf(v1, h1.x, a1x);  a1y = fmaf(v1, h1.y, a1y);
        a0x = fmaf(v2, h2.x, a0x);  a0y = fmaf(v2, h2.y, a0y);
        a1x = fmaf(v3, h3.x, a1x);  a1y = fmaf(v3, h3.y, a1y);
    }
    for (; e < end; e++) {
        int2 c = g_edges[e];
        float v = __int_as_float(c.y);
        float2 hv = s2[(size_t)c.x * 32 + lane];
        a0x = fmaf(v, hv.x, a0x);
        a0y = fmaf(v, hv.y, a0y);
    }
    float ax = a0x + a1x;
    float ay = a0y + a1y;

    const float escale = 1.0f + eps[0];
    const float2 b = reinterpret_cast<const float2*>(bias + phase * HALF)[lane];
    const float2 hs = s2[(size_t)node * 32 + lane];

    float2 ov;
    ov.x = fmaxf(fmaf(escale, hs.x, ax + b.x), 0.f);
    ov.y = fmaxf(fmaf(escale, hs.y, ay + b.y), 0.f);

    reinterpret_cast<float2*>(out)[(size_t)node * 64 + phase * 32 + lane] = ov;
}

// ---------------------------------------------------------------------------
// K7: copy h[:,64:128] from d_out into g_s (before phase B).
// ---------------------------------------------------------------------------
__global__ __launch_bounds__(256) void gin_copy_kernel(
    const float* __restrict__ h_src, int n_nodes)
{
    int idx = blockIdx.x * blockDim.x + threadIdx.x;   // over n_nodes*16 float4
    if (idx >= n_nodes * 16) return;
    int i = idx >> 4;
    int l = idx & 15;
    reinterpret_cast<float4*>(g_s)[idx] =
        reinterpret_cast<const float4*>(h_src)[i * 32 + 16 + l];
}

// ---------------------------------------------------------------------------
extern "C" void kernel_launch(void* const* d_in, const int* in_sizes, int n_in,
                              void* d_out, int out_size)
{
    const float* x     = (const float*)d_in[0];
    const float* W     = (const float*)d_in[1];
    const float* bias  = (const float*)d_in[2];
    const float* eps   = (const float*)d_in[3];
    const float* vals  = (const float*)d_in[4];
    const int*   row   = (const int*)d_in[5];
    const int*   col   = (const int*)d_in[6];
    float* out = (float*)d_out;

    const int n_nodes = in_sizes[0] / UNITS;
    const int n_edges = in_sizes[4];

    // CSR build
    gin_zero_kernel<<<(n_nodes + 255) / 256, 256>>>(n_nodes);
    gin_hist_kernel<<<(n_edges + 255) / 256, 256>>>(row, n_edges);
    gin_scan_kernel<<<1, 1024>>>(n_nodes);
    gin_scatter_kernel<<<(n_edges + 255) / 256, 256>>>(vals, row, col, n_edges);

    // h = x @ W  -> d_out (full) + g_s (cols 0:64)
    gin_gemm_kernel<<<(n_nodes + TM - 1) / TM, 256>>>(x, W, out, n_nodes);

    int agg_grid = (int)(((long long)n_nodes * 32 + 255) / 256);
    // Phase A: finalize out[:,0:64] (g_s holds h[:,0:64])
    gin_agg_kernel<<<agg_grid, 256>>>(bias, eps, out, n_nodes, 0);
    // Stash h[:,64:128] (still intact in d_out) into g_s
    gin_copy_kernel<<<(n_nodes * 16 + 255) / 256, 256>>>(out, n_nodes);
    // Phase B: finalize out[:,64:128]
    gin_agg_kernel<<<agg_grid, 256>>>(bias, eps, out, n_nodes, 1);
}

// round 11
// speedup vs baseline: 1.6758x; 1.6758x over previous
#include <cuda_runtime.h>
#include <cuda_bf16.h>
#include <cstdint>

// ---------------------------------------------------------------------------
// GINConvolution, refactored via linearity of the GEMM:
//   out = relu((1+eps)(xW) + A(xW) + b) = relu(((1+eps)x + Ax) W + b)
// Pipeline:
//   CSR build (zero,hist,bsum,bscan,off,scatter)   [statics: 15.2 MB only]
//   agg_x : y = (1+eps)*x + A*x  -> written to d_out  (CSR gather, no atomics)
//   gemm  : d_out = relu(d_out @ W + b)  in place (block reads own rows first)
// ---------------------------------------------------------------------------

#define N_NODES_MAX 100000
#define N_EDGES_MAX 1600000
#define UNITS 128
#define SCAN_B 512   // nodes per scan block

__device__ int  g_cnt[N_NODES_MAX];
__device__ int  g_off[N_NODES_MAX + 1];
__device__ int  g_cur[N_NODES_MAX];
__device__ int  g_bsum[(N_NODES_MAX + SCAN_B - 1) / SCAN_B];
__device__ int  g_boff[(N_NODES_MAX + SCAN_B - 1) / SCAN_B];
__device__ int2 g_edges[N_EDGES_MAX];     // (col, val-bits)

// ---------------------------------------------------------------------------
// K1: zero counters
// ---------------------------------------------------------------------------
__global__ __launch_bounds__(256) void gin_zero_kernel(int n_nodes)
{
    int i = blockIdx.x * blockDim.x + threadIdx.x;
    if (i < n_nodes) g_cnt[i] = 0;
}

// ---------------------------------------------------------------------------
// K2: histogram of row indices
// ---------------------------------------------------------------------------
__global__ __launch_bounds__(256) void gin_hist_kernel(
    const int* __restrict__ row, int n_edges)
{
    int e = blockIdx.x * blockDim.x + threadIdx.x;
    if (e < n_edges) atomicAdd(&g_cnt[row[e]], 1);
}

// ---------------------------------------------------------------------------
// K3: per-block sums of g_cnt (coalesced) -> g_bsum
// ---------------------------------------------------------------------------
__global__ __launch_bounds__(SCAN_B) void gin_bsum_kernel(int n_nodes)
{
    __shared__ int sh[SCAN_B];
    int i = blockIdx.x * SCAN_B + threadIdx.x;
    sh[threadIdx.x] = (i < n_nodes) ? g_cnt[i] : 0;
    __syncthreads();
    for (int off = SCAN_B / 2; off > 0; off >>= 1) {
        if (threadIdx.x < off) sh[threadIdx.x] += sh[threadIdx.x + off];
        __syncthreads();
    }
    if (threadIdx.x == 0) g_bsum[blockIdx.x] = sh[0];
}

// ---------------------------------------------------------------------------
// K4: single-block exclusive scan of g_bsum -> g_boff; writes g_off[n_nodes]
// ---------------------------------------------------------------------------
__global__ __launch_bounds__(256) void gin_bscan_kernel(int nb, int n_nodes)
{
    __shared__ int sh[256];
    int t = threadIdx.x;
    sh[t] = (t < nb) ? g_bsum[t] : 0;
    __syncthreads();
    for (int off = 1; off < 256; off <<= 1) {
        int v = (t >= off) ? sh[t - off] : 0;
        __syncthreads();
        sh[t] += v;
        __syncthreads();
    }
    if (t < nb) g_boff[t] = (t == 0) ? 0 : sh[t - 1];
    if (t == 0) g_off[n_nodes] = sh[255];
}

// ---------------------------------------------------------------------------
// K5: per-block exclusive scan of g_cnt + block base -> g_off, g_cur
// ---------------------------------------------------------------------------
__global__ __launch_bounds__(SCAN_B) void gin_off_kernel(int n_nodes)
{
    __shared__ int sh[SCAN_B];
    int t = threadIdx.x;
    int i = blockIdx.x * SCAN_B + t;
    int my = (i < n_nodes) ? g_cnt[i] : 0;
    sh[t] = my;
    __syncthreads();
    for (int off = 1; off < SCAN_B; off <<= 1) {
        int v = (t >= off) ? sh[t - off] : 0;
        __syncthreads();
        sh[t] += v;
        __syncthreads();
    }
    if (i < n_nodes) {
        int excl = g_boff[blockIdx.x] + sh[t] - my;
        g_off[i] = excl;
        g_cur[i] = excl;
    }
}

// ---------------------------------------------------------------------------
// K6: scatter edges into CSR order (packed 8B records)
// ---------------------------------------------------------------------------
__global__ __launch_bounds__(256) void gin_scatter_kernel(
    const float* __restrict__ vals,
    const int* __restrict__ row,
    const int* __restrict__ col,
    int n_edges)
{
    int e = blockIdx.x * blockDim.x + threadIdx.x;
    if (e >= n_edges) return;
    int r = row[e];
    int pos = atomicAdd(&g_cur[r], 1);
    g_edges[pos] = make_int2(col[e], __float_as_int(vals[e]));
}

// ---------------------------------------------------------------------------
// K7: x-space aggregation. Warp per node, lane handles float4 (128 cols).
//   y[node] = (1+eps)*x[node] + sum_e val * x[col_e]   -> d_out
// Unroll-2 edge loop for load parallelism.
// ---------------------------------------------------------------------------
__global__ __launch_bounds__(256) void gin_aggx_kernel(
    const float* __restrict__ x,
    const float* __restrict__ eps,
    float* __restrict__ y,
    int n_nodes)
{
    const int node = (blockIdx.x * blockDim.x + threadIdx.x) >> 5;
    if (node >= n_nodes) return;
    const int lane = threadIdx.x & 31;

    const int beg = g_off[node];
    const int end = g_off[node + 1];

    const float4* x4 = reinterpret_cast<const float4*>(x);

    float4 a0 = make_float4(0.f, 0.f, 0.f, 0.f);
    float4 a1 = make_float4(0.f, 0.f, 0.f, 0.f);

    int e = beg;
    for (; e + 2 <= end; e += 2) {
        int2 c0 = g_edges[e + 0];
        int2 c1 = g_edges[e + 1];
        float4 h0 = x4[(size_t)c0.x * 32 + lane];
        float4 h1 = x4[(size_t)c1.x * 32 + lane];
        float v0 = __int_as_float(c0.y);
        float v1 = __int_as_float(c1.y);
        a0.x = fmaf(v0, h0.x, a0.x); a0.y = fmaf(v0, h0.y, a0.y);
        a0.z = fmaf(v0, h0.z, a0.z); a0.w = fmaf(v0, h0.w, a0.w);
        a1.x = fmaf(v1, h1.x, a1.x); a1.y = fmaf(v1, h1.y, a1.y);
        a1.z = fmaf(v1, h1.z, a1.z); a1.w = fmaf(v1, h1.w, a1.w);
    }
    if (e < end) {
        int2 c = g_edges[e];
        float v = __int_as_float(c.y);
        float4 hv = x4[(size_t)c.x * 32 + lane];
        a0.x = fmaf(v, hv.x, a0.x); a0.y = fmaf(v, hv.y, a0.y);
        a0.z = fmaf(v, hv.z, a0.z); a0.w = fmaf(v, hv.w, a0.w);
    }

    const float es = 1.0f + eps[0];
    float4 xv = x4[(size_t)node * 32 + lane];
    float4 yv;
    yv.x = fmaf(es, xv.x, a0.x + a1.x);
    yv.y = fmaf(es, xv.y, a0.y + a1.y);
    yv.z = fmaf(es, xv.z, a0.z + a1.z);
    yv.w = fmaf(es, xv.w, a0.w + a1.w);
    reinterpret_cast<float4*>(y)[(size_t)node * 32 + lane] = yv;
}

// ---------------------------------------------------------------------------
// K8: in-place GEMM + epilogue:  y_rows = relu(y_rows @ W + b)
// Proven R1 structure (TM=64, 256 thr, FFMA, ~78 regs). Each block reads its
// own 64 rows into smem, syncs, computes, writes back the SAME rows only —
// in-place safe.
// ---------------------------------------------------------------------------
#define TM 64

__global__ __launch_bounds__(256) void gin_gemm_kernel(
    float* __restrict__ y,
    const float* __restrict__ W,
    const float* __restrict__ bias,
    int n_nodes)
{
    __shared__ float xs[TM][UNITS];

    const int block_row = blockIdx.x * TM;
    const int tid = threadIdx.x;

    {   // load y tile as float4 (zero-pad tail rows)
        const float4* y4 = reinterpret_cast<const float4*>(y);
        float4* xs4 = reinterpret_cast<float4*>(&xs[0][0]);
        for (int i = tid; i < TM * 32; i += 256) {
            int gr = block_row + (i >> 5);
            float4 v = make_float4(0.f, 0.f, 0.f, 0.f);
            if (gr < n_nodes) v = y4[gr * 32 + (i & 31)];
            xs4[i] = v;
        }
    }
    __syncthreads();

    const int tx = tid & 31;   // 4 cols: 4tx..4tx+3
    const int ty = tid >> 5;   // 8 rows: ty + 8i

    float acc[8][4];
    #pragma unroll
    for (int i = 0; i < 8; i++)
        #pragma unroll
        for (int j = 0; j < 4; j++) acc[i][j] = 0.f;

    const float4* W4 = reinterpret_cast<const float4*>(W);

    #pragma unroll 4
    for (int k = 0; k < UNITS; k++) {
        float4 w = W4[k * 32 + tx];
        #pragma unroll
        for (int i = 0; i < 8; i++) {
            float a = xs[ty + 8 * i][k];   // warp-broadcast
            acc[i][0] += a * w.x;
            acc[i][1] += a * w.y;
            acc[i][2] += a * w.z;
            acc[i][3] += a * w.w;
        }
    }

    const float4 b = reinterpret_cast<const float4*>(bias)[tx];
    float4* o4 = reinterpret_cast<float4*>(y);

    #pragma unroll
    for (int i = 0; i < 8; i++) {
        int gr = block_row + ty + 8 * i;
        if (gr < n_nodes) {
            float4 ov;
            ov.x = fmaxf(acc[i][0] + b.x, 0.f);
            ov.y = fmaxf(acc[i][1] + b.y, 0.f);
            ov.z = fmaxf(acc[i][2] + b.z, 0.f);
            ov.w = fmaxf(acc[i][3] + b.w, 0.f);
            o4[gr * 32 + tx] = ov;
        }
    }
}

// ---------------------------------------------------------------------------
extern "C" void kernel_launch(void* const* d_in, const int* in_sizes, int n_in,
                              void* d_out, int out_size)
{
    const float* x     = (const float*)d_in[0];
    const float* W     = (const float*)d_in[1];
    const float* bias  = (const float*)d_in[2];
    const float* eps   = (const float*)d_in[3];
    const float* vals  = (const float*)d_in[4];
    const int*   row   = (const int*)d_in[5];
    const int*   col   = (const int*)d_in[6];
    float* out = (float*)d_out;

    const int n_nodes = in_sizes[0] / UNITS;
    const int n_edges = in_sizes[4];
    const int nb = (n_nodes + SCAN_B - 1) / SCAN_B;

    // CSR build (all coalesced / small)
    gin_zero_kernel<<<(n_nodes + 255) / 256, 256>>>(n_nodes);
    gin_hist_kernel<<<(n_edges + 255) / 256, 256>>>(row, n_edges);
    gin_bsum_kernel<<<nb, SCAN_B>>>(n_nodes);
    gin_bscan_kernel<<<1, 256>>>(nb, n_nodes);
    gin_off_kernel<<<nb, SCAN_B>>>(n_nodes);
    gin_scatter_kernel<<<(n_edges + 255) / 256, 256>>>(vals, row, col, n_edges);

    // y = (1+eps)x + Ax  -> d_out
    {
        long long total = (long long)n_nodes * 32;
        int grid = (int)((total + 255) / 256);
        gin_aggx_kernel<<<grid, 256>>>(x, eps, out, n_nodes);
    }

    // out = relu(y @ W + b), in place
    gin_gemm_kernel<<<(n_nodes + TM - 1) / TM, 256>>>(out, W, bias, n_nodes);
}